// round 14
// baseline (speedup 1.0000x reference)
#include <cuda_runtime.h>
#include <cstdint>

#define DNF  133
#define DPAD 136   // padded feature stride: 544 B rows, float4-aligned
#define MAXN 50000
#define MAXE 800000
#define NGRAPH 256
#define WDIM 136   // padded W dim for mma (17 n-tiles of 8, 17 k-steps of 8)
#define WSTR 160   // g_Whl row stride (float2): lane+32q<=159 always in-bounds
#define LDW  160   // smem row stride (float2): unpredicated stores, 40KB total

// ---------------- static device scratch (zero-initialized at load) ----------------
__device__ float g_hp[MAXN * DPAD];    // (X@W) * dinv[row]; cols 133..135 stay 0
__device__ float g_feat[MAXN * DPAD];  // layer outputs;     cols 133..135 stay 0
__device__ int   g_deg[MAXN];
__device__ int   g_rowptr[MAXN + 1];
__device__ int   g_pos[MAXN];
__device__ int   g_col[MAXE];
__device__ int   g_bsum[256];
__device__ int   g_is64;
// W split into tf32 (hi,lo) float2 pairs, [k][n] stride-160, zero-padded
__device__ float2 g_Whl[2][WDIM * WSTR];

// ---------------- tf32 helpers ----------------
__device__ __forceinline__ uint32_t f2tf32(float f) {
    uint32_t u;
    asm("cvt.rna.tf32.f32 %0, %1;" : "=r"(u) : "f"(f));
    return u;
}
// D(16x8,f32) += A(16x8,tf32,row) * B(8x8,tf32,col)
#define MMA_TF32(d, a, b0, b1) \
    asm("mma.sync.aligned.m16n8k8.row.col.f32.tf32.tf32.f32 " \
        "{%0,%1,%2,%3}, {%4,%5,%6,%7}, {%8,%9}, {%0,%1,%2,%3};" \
        : "+f"((d)[0]), "+f"((d)[1]), "+f"((d)[2]), "+f"((d)[3]) \
        : "r"((a)[0]), "r"((a)[1]), "r"((a)[2]), "r"((a)[3]), "r"(b0), "r"(b1))

// ---------------- prologue: deg=1 (self loop) + dtype detect ----------------
__global__ void prologue_kernel(const int* __restrict__ w, int n) {
    int i = blockIdx.x * blockDim.x + threadIdx.x;
    if (i < n) g_deg[i] = 1;
    if (blockIdx.x == 0 && threadIdx.x < 32) {
        int lane = threadIdx.x;
        int bad = 0;
#pragma unroll
        for (int it = 0; it < 32; it++)
            bad |= w[2 * (lane + 32 * it) + 1];
        unsigned any = __ballot_sync(0xffffffffu, bad != 0);
        if (lane == 0) g_is64 = (any == 0u) ? 1 : 0;
    }
}

__device__ __forceinline__ int load_idx(const void* p, long long i) {
    return g_is64 ? (int)((const long long*)p)[i] : ((const int*)p)[i];
}

__global__ void count_deg_kernel(const void* __restrict__ ei, int e) {
    int i = blockIdx.x * blockDim.x + threadIdx.x;
    if (i < e) atomicAdd(&g_deg[load_idx(ei, (long long)e + i)], 1);
}

// ---------------- W split: g_Whl[w][k*WSTR+n] = (tf32_hi, tf32_lo) of W[k][n] ----------------
__global__ void wconv_kernel(const float* __restrict__ W1,
                             const float* __restrict__ W2) {
    int k = blockIdx.x, w = blockIdx.y, nn = threadIdx.x;
    if (nn >= WDIM) return;          // cols 136..159 stay zero (static init)
    const float* W = w ? W2 : W1;
    float v = (k < DNF && nn < DNF) ? W[k * DNF + nn] : 0.f;
    uint32_t uh = f2tf32(v);
    float vh = __uint_as_float(uh);
    uint32_t ul = f2tf32(v - vh);
    g_Whl[w][k * WSTR + nn] = make_float2(vh, __uint_as_float(ul));
}

// ---------------- 2-level parallel exclusive scan of (deg-1) ----------------
__global__ void partial_kernel(int n) {
    __shared__ int wsum[8];
    int i = blockIdx.x * blockDim.x + threadIdx.x;
    int d = (i < n) ? g_deg[i] - 1 : 0;
    int lane = threadIdx.x & 31, wid = threadIdx.x >> 5;
#pragma unroll
    for (int o = 16; o > 0; o >>= 1) d += __shfl_down_sync(0xffffffffu, d, o);
    if (lane == 0) wsum[wid] = d;
    __syncthreads();
    if (wid == 0) {
        int s = (lane < 8) ? wsum[lane] : 0;
#pragma unroll
        for (int o = 4; o > 0; o >>= 1) s += __shfl_down_sync(0xffffffffu, s, o);
        if (lane == 0) g_bsum[blockIdx.x] = s;
    }
}

__global__ void finalize_kernel(int n, int e) {
    __shared__ int wsum[8];
    __shared__ int off_s;
    int tid = threadIdx.x, bid = blockIdx.x;
    int lane = tid & 31, wid = tid >> 5;
    {
        int v = (tid < bid) ? g_bsum[tid] : 0;
#pragma unroll
        for (int o = 16; o > 0; o >>= 1) v += __shfl_down_sync(0xffffffffu, v, o);
        if (lane == 0) wsum[wid] = v;
        __syncthreads();
        if (wid == 0) {
            int s = (lane < 8) ? wsum[lane] : 0;
#pragma unroll
            for (int o = 4; o > 0; o >>= 1) s += __shfl_down_sync(0xffffffffu, s, o);
            if (lane == 0) off_s = s;
        }
        __syncthreads();
    }
    int offset = off_s;
    __syncthreads();

    int i = bid * blockDim.x + tid;
    int deg = (i < n) ? g_deg[i] : 1;
    int d = (i < n) ? deg - 1 : 0;
    int v = d;
#pragma unroll
    for (int o = 1; o < 32; o <<= 1) {
        int t = __shfl_up_sync(0xffffffffu, v, o);
        if (lane >= o) v += t;
    }
    if (lane == 31) wsum[wid] = v;
    __syncthreads();
    if (wid == 0) {
        int s = (lane < 8) ? wsum[lane] : 0;
#pragma unroll
        for (int o = 1; o < 8; o <<= 1) {
            int t = __shfl_up_sync(0xffffffffu, s, o);
            if (lane >= o) s += t;
        }
        if (lane < 8) wsum[lane] = s;
    }
    __syncthreads();
    int excl = v - d + ((wid > 0) ? wsum[wid - 1] : 0);
    if (i < n) {
        int rp = offset + excl;
        g_rowptr[i] = rp;
        g_pos[i] = rp;
    }
    if (i == 0) g_rowptr[n] = e;
}

__global__ void fill_kernel(const void* __restrict__ ei, int e) {
    int i = blockIdx.x * blockDim.x + threadIdx.x;
    if (i < e) {
        int sidx = load_idx(ei, i);
        int d    = load_idx(ei, (long long)e + i);
        g_col[atomicAdd(&g_pos[d], 1)] = sidx;
    }
}

// ---------------- tensor-core GEMM (tf32 split, double-buffered W, direct-A) ----------------
// Block: 256 threads = 8 warps, 128 rows x 136 cols. Warp = 16-row strip.
// A-fragments thread-exclusive, straight from gmem. W staged in double-buffered
// smem as (hi,lo) float2, UNPREDICATED fills (strides padded to 160).
// __launch_bounds__(256,2): regs <= 128 -> 2 CTAs/SM -> cross-CTA latency hiding.
__global__ void __launch_bounds__(256, 2)
gemm_mma_kernel(const float* __restrict__ Xext, int widx, int use_ext, int n) {
    __shared__ float2 Wbuf[2][16 * LDW];   // 2 x 20480 B = 40 KB

    const float* X = use_ext ? Xext : (const float*)g_feat;
    int ldx = use_ext ? DNF : DPAD;
    const float2* Whl = g_Whl[widx];

    int tid = threadIdx.x;
    int lane = tid & 31, warp = tid >> 5;
    int row0 = blockIdx.x * 128;
    int strip = warp * 16;
    int gid = lane >> 2;    // 0..7
    int tig = lane & 3;     // 0..3

    int ra = row0 + strip + gid;
    int rb = ra + 8;
    bool va = (ra < n), vb = (rb < n);
    const float* Xa = X + (size_t)(va ? ra : 0) * ldx;
    const float* Xb = X + (size_t)(vb ? rb : 0) * ldx;

    float acc[17][4];
#pragma unroll
    for (int t = 0; t < 17; t++)
#pragma unroll
        for (int j = 0; j < 4; j++) acc[t][j] = 0.f;

    float  xr[2][8];        // [parity][ks*4 + {a0,b0,a1,b1}]
    float2 wld[2][5];       // W prefetch regs: 2 k-rows x 5 col-groups

    // ---- prologue: chunk 0 ----
#pragma unroll
    for (int ks = 0; ks < 2; ks++) {
        int c0 = 8 * ks + tig, c1 = c0 + 4;
        xr[0][4 * ks + 0] = va ? Xa[c0] : 0.f;    // k < 16 < DNF
        xr[0][4 * ks + 1] = vb ? Xb[c0] : 0.f;
        xr[0][4 * ks + 2] = va ? Xa[c1] : 0.f;
        xr[0][4 * ks + 3] = vb ? Xb[c1] : 0.f;
    }
#pragma unroll
    for (int rr = 0; rr < 2; rr++) {
        const float2* wp = Whl + (size_t)(warp * 2 + rr) * WSTR;
#pragma unroll
        for (int q = 0; q < 5; q++)
            wld[rr][q] = wp[lane + 32 * q];       // unpredicated, stride-160
    }
#pragma unroll
    for (int rr = 0; rr < 2; rr++)
#pragma unroll
        for (int q = 0; q < 5; q++)
            Wbuf[0][(warp * 2 + rr) * LDW + lane + 32 * q] = wld[rr][q];
    __syncthreads();

#pragma unroll
    for (int ch = 0; ch < 9; ch++) {
        const int cur = ch & 1, nxt = cur ^ 1;

        // ---- issue gmem prefetch for chunk ch+1 (drains behind MMAs) ----
        if (ch < 8) {
            int k0 = (ch + 1) * 16;
#pragma unroll
            for (int ks = 0; ks < 2; ks++) {
                int c0 = k0 + 8 * ks + tig, c1 = c0 + 4;
                xr[nxt][4 * ks + 0] = (va && c0 < DNF) ? Xa[c0] : 0.f;
                xr[nxt][4 * ks + 1] = (vb && c0 < DNF) ? Xb[c0] : 0.f;
                xr[nxt][4 * ks + 2] = (va && c1 < DNF) ? Xa[c1] : 0.f;
                xr[nxt][4 * ks + 3] = (vb && c1 < DNF) ? Xb[c1] : 0.f;
            }
#pragma unroll
            for (int rr = 0; rr < 2; rr++) {
                int k = k0 + warp * 2 + rr;
                bool kv = (k < WDIM);             // rows >= WDIM must be zero
                const float2* wp = Whl + (size_t)(kv ? k : 0) * WSTR;
#pragma unroll
                for (int q = 0; q < 5; q++) {
                    float2 v = wp[lane + 32 * q];
                    wld[rr][q] = kv ? v : make_float2(0.f, 0.f);
                }
            }
        }

        // ---- MMAs for chunk ch ----
#pragma unroll
        for (int ks = 0; ks < 2; ks++) {
            float x00 = xr[cur][4 * ks + 0];
            float x10 = xr[cur][4 * ks + 1];
            float x01 = xr[cur][4 * ks + 2];
            float x11 = xr[cur][4 * ks + 3];
            uint32_t ah[4], al[4];
            ah[0] = f2tf32(x00); al[0] = f2tf32(x00 - __uint_as_float(ah[0]));
            ah[1] = f2tf32(x10); al[1] = f2tf32(x10 - __uint_as_float(ah[1]));
            ah[2] = f2tf32(x01); al[2] = f2tf32(x01 - __uint_as_float(ah[2]));
            ah[3] = f2tf32(x11); al[3] = f2tf32(x11 - __uint_as_float(ah[3]));

            int rb0 = (8 * ks + tig) * LDW;
            int rb1 = (8 * ks + tig + 4) * LDW;
#pragma unroll
            for (int nt = 0; nt < 17; nt++) {
                int nb = nt * 8 + gid;
                float2 b0 = Wbuf[cur][rb0 + nb];
                float2 b1 = Wbuf[cur][rb1 + nb];
                MMA_TF32(acc[nt], ah, __float_as_uint(b0.x), __float_as_uint(b1.x));
                MMA_TF32(acc[nt], ah, __float_as_uint(b0.y), __float_as_uint(b1.y));
                MMA_TF32(acc[nt], al, __float_as_uint(b0.x), __float_as_uint(b1.x));
            }
        }

        // ---- store W(ch+1) into the other buffer; single barrier ----
        if (ch < 8) {
#pragma unroll
            for (int rr = 0; rr < 2; rr++)
#pragma unroll
                for (int q = 0; q < 5; q++)
                    Wbuf[nxt][(warp * 2 + rr) * LDW + lane + 32 * q] = wld[rr][q];
            __syncthreads();
        }
    }

    // ---- epilogue: D thread layout (gid, 2*tig),(.,+1),(gid+8, 2*tig),(.,+1) ----
    float d0 = va ? rsqrtf((float)g_deg[ra]) : 0.f;
    float d1 = vb ? rsqrtf((float)g_deg[rb]) : 0.f;
#pragma unroll
    for (int nt = 0; nt < 17; nt++) {
        int c0 = nt * 8 + 2 * tig;
        if (va)
            *(float2*)(g_hp + (size_t)ra * DPAD + c0) =
                make_float2(acc[nt][0] * d0, acc[nt][1] * d0);
        if (vb)
            *(float2*)(g_hp + (size_t)rb * DPAD + c0) =
                make_float2(acc[nt][2] * d1, acc[nt][3] * d1);
    }
}

// ---------------- aggregate: g_feat[i] = relu(dinv[i]*(sum_in hp[j] + hp[i]) + b) ----------------
__global__ void aggregate_kernel(const float* __restrict__ bias, int n) {
    int node = blockIdx.x * (blockDim.x >> 5) + (threadIdx.x >> 5);
    if (node >= n) return;
    int lane = threadIdx.x & 31;

    const float4* self4 = (const float4*)(g_hp + (size_t)node * DPAD);
    float4 acc = self4[lane];
    float4 acct = make_float4(0.f, 0.f, 0.f, 0.f);
    if (lane < 2) acct = self4[32 + lane];

    int s = g_rowptr[node], e = g_rowptr[node + 1];
    int idx = s;
    for (; idx + 1 < e; idx += 2) {
        int j0 = g_col[idx], j1 = g_col[idx + 1];
        const float4* r0 = (const float4*)(g_hp + (size_t)j0 * DPAD);
        const float4* r1 = (const float4*)(g_hp + (size_t)j1 * DPAD);
        float4 v0 = r0[lane];
        float4 v1 = r1[lane];
        float4 t0, t1;
        if (lane < 2) { t0 = r0[32 + lane]; t1 = r1[32 + lane]; }
        acc.x += v0.x; acc.y += v0.y; acc.z += v0.z; acc.w += v0.w;
        acc.x += v1.x; acc.y += v1.y; acc.z += v1.z; acc.w += v1.w;
        if (lane < 2) {
            acct.x += t0.x; acct.y += t0.y; acct.z += t0.z; acct.w += t0.w;
            acct.x += t1.x; acct.y += t1.y; acct.z += t1.z; acct.w += t1.w;
        }
    }
    if (idx < e) {
        int j0 = g_col[idx];
        const float4* r0 = (const float4*)(g_hp + (size_t)j0 * DPAD);
        float4 v0 = r0[lane];
        acc.x += v0.x; acc.y += v0.y; acc.z += v0.z; acc.w += v0.w;
        if (lane < 2) {
            float4 t0 = r0[32 + lane];
            acct.x += t0.x; acct.y += t0.y; acct.z += t0.z; acct.w += t0.w;
        }
    }

    float di = rsqrtf((float)g_deg[node]);
    float4 o;
    o.x = fmaxf(fmaf(acc.x, di, bias[4 * lane + 0]), 0.f);
    o.y = fmaxf(fmaf(acc.y, di, bias[4 * lane + 1]), 0.f);
    o.z = fmaxf(fmaf(acc.z, di, bias[4 * lane + 2]), 0.f);
    o.w = fmaxf(fmaf(acc.w, di, bias[4 * lane + 3]), 0.f);
    float4* out4 = (float4*)(g_feat + (size_t)node * DPAD);
    out4[lane] = o;
    if (lane == 0) {
        float4 t;
        t.x = fmaxf(fmaf(acct.x, di, bias[128]), 0.f);
        t.y = fmaxf(fmaf(acct.y, di, bias[129]), 0.f);
        t.z = fmaxf(fmaf(acct.z, di, bias[130]), 0.f);
        t.w = fmaxf(fmaf(acct.w, di, bias[131]), 0.f);
        out4[32] = t;
    } else if (lane == 1) {
        float4 t;
        t.x = fmaxf(fmaf(acct.x, di, bias[132]), 0.f);
        t.y = 0.f; t.z = 0.f; t.w = 0.f;   // keep pads zero
        out4[33] = t;
    }
}

// ---------------- global mean pool ----------------
__device__ __forceinline__ int lbound_any(const void* a, int n, int v) {
    int lo = 0, hi = n;
    while (lo < hi) {
        int m = (lo + hi) >> 1;
        long long x = g_is64 ? ((const long long*)a)[m]
                             : (long long)((const int*)a)[m];
        if (x < (long long)v) lo = m + 1; else hi = m;
    }
    return lo;
}

__global__ void pool_kernel(const void* __restrict__ batch,
                            float* __restrict__ out, int n) {
    __shared__ int lo_s, hi_s;
    int g = blockIdx.x;
    if (threadIdx.x == 0) {
        lo_s = lbound_any(batch, n, g);
        hi_s = lbound_any(batch, n, g + 1);
    }
    __syncthreads();
    int lo = lo_s, hi = hi_s;
    int c = threadIdx.x;
    if (c < DNF) {
        float s0 = 0.f, s1 = 0.f, s2 = 0.f, s3 = 0.f;
        int r = lo;
        for (; r + 3 < hi; r += 4) {
            s0 += g_feat[(size_t)(r + 0) * DPAD + c];
            s1 += g_feat[(size_t)(r + 1) * DPAD + c];
            s2 += g_feat[(size_t)(r + 2) * DPAD + c];
            s3 += g_feat[(size_t)(r + 3) * DPAD + c];
        }
        for (; r < hi; r++) s0 += g_feat[(size_t)r * DPAD + c];
        int cnt = hi - lo;
        out[g * DNF + c] = ((s0 + s1) + (s2 + s3)) / (float)(cnt > 0 ? cnt : 1);
    }
}

// ---------------- launch: kernel launches ONLY ----------------
extern "C" void kernel_launch(void* const* d_in, const int* in_sizes, int n_in,
                              void* d_out, int out_size) {
    const float* x     = (const float*)d_in[0];
    const void*  ei    = d_in[1];
    const void*  batch = d_in[2];
    const float* W1    = (const float*)d_in[3];
    const float* b1    = (const float*)d_in[4];
    const float* W2    = (const float*)d_in[5];
    const float* b2    = (const float*)d_in[6];
    float* out = (float*)d_out;

    int n = in_sizes[0] / DNF;   // 50000
    int e = in_sizes[1] / 2;     // 800000

    int tb = 256;
    int gn = (n + tb - 1) / tb;  // 196
    int ge = (e + tb - 1) / tb;

    int gemm_blocks = (n + 127) / 128;   // 391
    int agg_blocks  = (n + 7) / 8;

    prologue_kernel<<<gn, tb>>>((const int*)ei, n);       // 1: deg=1 + dtype detect
    count_deg_kernel<<<ge, tb>>>(ei, e);                  // 2
    wconv_kernel<<<dim3(WDIM, 2), 160>>>(W1, W2);         // 3: tf32 (hi,lo) pack
    gemm_mma_kernel<<<gemm_blocks, 256>>>(x, 0, 1, n);    // 4 <- profiled slot
    partial_kernel<<<gn, tb>>>(n);                        // 5
    finalize_kernel<<<gn, tb>>>(n, e);                    // 6: rowptr+pos
    fill_kernel<<<ge, tb>>>(ei, e);                       // 7
    aggregate_kernel<<<agg_blocks, 256>>>(b1, n);         // 8
    gemm_mma_kernel<<<gemm_blocks, 256>>>(x, 1, 0, n);    // 9
    aggregate_kernel<<<agg_blocks, 256>>>(b2, n);         // 10
    pool_kernel<<<NGRAPH, 160>>>(batch, out, n);          // 11
}

// round 15
// speedup vs baseline: 1.3261x; 1.3261x over previous
#include <cuda_runtime.h>
#include <cstdint>

#define DNF  133
#define DPAD 136   // padded feature stride: 544 B rows, float4-aligned
#define MAXN 50000
#define MAXE 800000
#define NGRAPH 256
#define WDIM 136   // real W columns
#define WSTR 160   // g_Whl row stride (float2), cols 136..159 zero
#define NT   9     // n-tiles per half (9 x 8 = 72 cols; N padded to 144)
#define LDW2 76    // smem row stride (float2): 152 words % 32 = 24 -> staggered banks

// ---------------- static device scratch (zero-initialized at load) ----------------
__device__ float g_hp[MAXN * DPAD];    // (X@W) * dinv[row]; cols 133..135 stay 0
__device__ float g_feat[MAXN * DPAD];  // layer outputs;     cols 133..135 stay 0
__device__ int   g_deg[MAXN];
__device__ int   g_rowptr[MAXN + 1];
__device__ int   g_pos[MAXN];
__device__ int   g_col[MAXE];
__device__ int   g_bsum[256];
__device__ int   g_is64;
// W split into tf32 (hi,lo) float2 pairs, [k][n] stride-160, zero-padded
__device__ float2 g_Whl[2][WDIM * WSTR];

// ---------------- tf32 helpers ----------------
__device__ __forceinline__ uint32_t f2tf32(float f) {
    uint32_t u;
    asm("cvt.rna.tf32.f32 %0, %1;" : "=r"(u) : "f"(f));
    return u;
}
// D(16x8,f32) += A(16x8,tf32,row) * B(8x8,tf32,col)
#define MMA_TF32(d, a, b0, b1) \
    asm("mma.sync.aligned.m16n8k8.row.col.f32.tf32.tf32.f32 " \
        "{%0,%1,%2,%3}, {%4,%5,%6,%7}, {%8,%9}, {%0,%1,%2,%3};" \
        : "+f"((d)[0]), "+f"((d)[1]), "+f"((d)[2]), "+f"((d)[3]) \
        : "r"((a)[0]), "r"((a)[1]), "r"((a)[2]), "r"((a)[3]), "r"(b0), "r"(b1))

// ---------------- prologue: deg=1 (self loop) + dtype detect ----------------
__global__ void prologue_kernel(const int* __restrict__ w, int n) {
    int i = blockIdx.x * blockDim.x + threadIdx.x;
    if (i < n) g_deg[i] = 1;
    if (blockIdx.x == 0 && threadIdx.x < 32) {
        int lane = threadIdx.x;
        int bad = 0;
#pragma unroll
        for (int it = 0; it < 32; it++)
            bad |= w[2 * (lane + 32 * it) + 1];
        unsigned any = __ballot_sync(0xffffffffu, bad != 0);
        if (lane == 0) g_is64 = (any == 0u) ? 1 : 0;
    }
}

__device__ __forceinline__ int load_idx(const void* p, long long i) {
    return g_is64 ? (int)((const long long*)p)[i] : ((const int*)p)[i];
}

__global__ void count_deg_kernel(const void* __restrict__ ei, int e) {
    int i = blockIdx.x * blockDim.x + threadIdx.x;
    if (i < e) atomicAdd(&g_deg[load_idx(ei, (long long)e + i)], 1);
}

// ---------------- W split: g_Whl[w][k*WSTR+n] = (tf32_hi, tf32_lo) of W[k][n] ----------------
__global__ void wconv_kernel(const float* __restrict__ W1,
                             const float* __restrict__ W2) {
    int k = blockIdx.x, w = blockIdx.y, nn = threadIdx.x;
    if (nn >= WDIM) return;          // cols 136..159 stay zero (static init)
    const float* W = w ? W2 : W1;
    float v = (k < DNF && nn < DNF) ? W[k * DNF + nn] : 0.f;
    uint32_t uh = f2tf32(v);
    float vh = __uint_as_float(uh);
    uint32_t ul = f2tf32(v - vh);
    g_Whl[w][k * WSTR + nn] = make_float2(vh, __uint_as_float(ul));
}

// ---------------- 2-level parallel exclusive scan of (deg-1) ----------------
__global__ void partial_kernel(int n) {
    __shared__ int wsum[8];
    int i = blockIdx.x * blockDim.x + threadIdx.x;
    int d = (i < n) ? g_deg[i] - 1 : 0;
    int lane = threadIdx.x & 31, wid = threadIdx.x >> 5;
#pragma unroll
    for (int o = 16; o > 0; o >>= 1) d += __shfl_down_sync(0xffffffffu, d, o);
    if (lane == 0) wsum[wid] = d;
    __syncthreads();
    if (wid == 0) {
        int s = (lane < 8) ? wsum[lane] : 0;
#pragma unroll
        for (int o = 4; o > 0; o >>= 1) s += __shfl_down_sync(0xffffffffu, s, o);
        if (lane == 0) g_bsum[blockIdx.x] = s;
    }
}

__global__ void finalize_kernel(int n, int e) {
    __shared__ int wsum[8];
    __shared__ int off_s;
    int tid = threadIdx.x, bid = blockIdx.x;
    int lane = tid & 31, wid = tid >> 5;
    {
        int v = (tid < bid) ? g_bsum[tid] : 0;
#pragma unroll
        for (int o = 16; o > 0; o >>= 1) v += __shfl_down_sync(0xffffffffu, v, o);
        if (lane == 0) wsum[wid] = v;
        __syncthreads();
        if (wid == 0) {
            int s = (lane < 8) ? wsum[lane] : 0;
#pragma unroll
            for (int o = 4; o > 0; o >>= 1) s += __shfl_down_sync(0xffffffffu, s, o);
            if (lane == 0) off_s = s;
        }
        __syncthreads();
    }
    int offset = off_s;
    __syncthreads();

    int i = bid * blockDim.x + tid;
    int deg = (i < n) ? g_deg[i] : 1;
    int d = (i < n) ? deg - 1 : 0;
    int v = d;
#pragma unroll
    for (int o = 1; o < 32; o <<= 1) {
        int t = __shfl_up_sync(0xffffffffu, v, o);
        if (lane >= o) v += t;
    }
    if (lane == 31) wsum[wid] = v;
    __syncthreads();
    if (wid == 0) {
        int s = (lane < 8) ? wsum[lane] : 0;
#pragma unroll
        for (int o = 1; o < 8; o <<= 1) {
            int t = __shfl_up_sync(0xffffffffu, s, o);
            if (lane >= o) s += t;
        }
        if (lane < 8) wsum[lane] = s;
    }
    __syncthreads();
    int excl = v - d + ((wid > 0) ? wsum[wid - 1] : 0);
    if (i < n) {
        int rp = offset + excl;
        g_rowptr[i] = rp;
        g_pos[i] = rp;
    }
    if (i == 0) g_rowptr[n] = e;
}

__global__ void fill_kernel(const void* __restrict__ ei, int e) {
    int i = blockIdx.x * blockDim.x + threadIdx.x;
    if (i < e) {
        int sidx = load_idx(ei, i);
        int d    = load_idx(ei, (long long)e + i);
        g_col[atomicAdd(&g_pos[d], 1)] = sidx;
    }
}

// ---------------- tensor-core GEMM (tf32 split, N-split halves) ----------------
// Grid (391, 2): blockIdx.y picks a 72-col half (N padded to 144 = 2 x 9 tiles).
// Block: 256 threads = 8 warps, 128 rows x 72 cols. acc[9][4] = 36 regs/thread
// -> ~100 regs -> 2 CTAs/SM without spills; cross-CTA latency hiding.
// A-fragments thread-exclusive straight from gmem; W double-buffered in smem.
__global__ void __launch_bounds__(256)
gemm_mma_kernel(const float* __restrict__ Xext, int widx, int use_ext, int n) {
    __shared__ float2 Wbuf[2][16 * LDW2];   // 2 x 9728 B

    const float* X = use_ext ? Xext : (const float*)g_feat;
    int ldx = use_ext ? DNF : DPAD;
    const float2* Whl = g_Whl[widx];
    int NB = blockIdx.y * (NT * 8);          // 0 or 72

    int tid = threadIdx.x;
    int lane = tid & 31, warp = tid >> 5;
    int row0 = blockIdx.x * 128;
    int strip = warp * 16;
    int gid = lane >> 2;    // 0..7
    int tig = lane & 3;     // 0..3

    int ra = row0 + strip + gid;
    int rb = ra + 8;
    bool va = (ra < n), vb = (rb < n);
    const float* Xa = X + (size_t)(va ? ra : 0) * ldx;
    const float* Xb = X + (size_t)(vb ? rb : 0) * ldx;

    float acc[NT][4];
#pragma unroll
    for (int t = 0; t < NT; t++)
#pragma unroll
        for (int j = 0; j < 4; j++) acc[t][j] = 0.f;

    float  xr[2][8];        // [parity][ks*4 + {a0,b0,a1,b1}]
    float2 wld[2][3];       // W prefetch: 2 k-rows x 3 col-groups (72 cols)

    // ---- prologue: chunk 0 ----
#pragma unroll
    for (int ks = 0; ks < 2; ks++) {
        int c0 = 8 * ks + tig, c1 = c0 + 4;
        xr[0][4 * ks + 0] = va ? Xa[c0] : 0.f;    // k < 16 < DNF
        xr[0][4 * ks + 1] = vb ? Xb[c0] : 0.f;
        xr[0][4 * ks + 2] = va ? Xa[c1] : 0.f;
        xr[0][4 * ks + 3] = vb ? Xb[c1] : 0.f;
    }
#pragma unroll
    for (int rr = 0; rr < 2; rr++) {
        const float2* wp = Whl + (size_t)(warp * 2 + rr) * WSTR + NB;
#pragma unroll
        for (int q = 0; q < 3; q++) {
            int cc = lane + 32 * q;
            wld[rr][q] = (cc < NT * 8) ? wp[cc] : make_float2(0.f, 0.f);
        }
    }
#pragma unroll
    for (int rr = 0; rr < 2; rr++)
#pragma unroll
        for (int q = 0; q < 3; q++) {
            int cc = lane + 32 * q;
            if (cc < NT * 8) Wbuf[0][(warp * 2 + rr) * LDW2 + cc] = wld[rr][q];
        }
    __syncthreads();

#pragma unroll
    for (int ch = 0; ch < 9; ch++) {
        const int cur = ch & 1, nxt = cur ^ 1;

        // ---- issue gmem prefetch for chunk ch+1 (drains behind MMAs) ----
        if (ch < 8) {
            int k0 = (ch + 1) * 16;
#pragma unroll
            for (int ks = 0; ks < 2; ks++) {
                int c0 = k0 + 8 * ks + tig, c1 = c0 + 4;
                xr[nxt][4 * ks + 0] = (va && c0 < DNF) ? Xa[c0] : 0.f;
                xr[nxt][4 * ks + 1] = (vb && c0 < DNF) ? Xb[c0] : 0.f;
                xr[nxt][4 * ks + 2] = (va && c1 < DNF) ? Xa[c1] : 0.f;
                xr[nxt][4 * ks + 3] = (vb && c1 < DNF) ? Xb[c1] : 0.f;
            }
#pragma unroll
            for (int rr = 0; rr < 2; rr++) {
                int k = k0 + warp * 2 + rr;
                bool kv = (k < WDIM);             // rows >= WDIM must be zero
                const float2* wp = Whl + (size_t)(kv ? k : 0) * WSTR + NB;
#pragma unroll
                for (int q = 0; q < 3; q++) {
                    int cc = lane + 32 * q;
                    float2 v = (cc < NT * 8) ? wp[cc] : make_float2(0.f, 0.f);
                    wld[rr][q] = kv ? v : make_float2(0.f, 0.f);
                }
            }
        }

        // ---- MMAs for chunk ch ----
#pragma unroll
        for (int ks = 0; ks < 2; ks++) {
            float x00 = xr[cur][4 * ks + 0];
            float x10 = xr[cur][4 * ks + 1];
            float x01 = xr[cur][4 * ks + 2];
            float x11 = xr[cur][4 * ks + 3];
            uint32_t ah[4], al[4];
            ah[0] = f2tf32(x00); al[0] = f2tf32(x00 - __uint_as_float(ah[0]));
            ah[1] = f2tf32(x10); al[1] = f2tf32(x10 - __uint_as_float(ah[1]));
            ah[2] = f2tf32(x01); al[2] = f2tf32(x01 - __uint_as_float(ah[2]));
            ah[3] = f2tf32(x11); al[3] = f2tf32(x11 - __uint_as_float(ah[3]));

            int rb0 = (8 * ks + tig) * LDW2;
            int rb1 = (8 * ks + tig + 4) * LDW2;
#pragma unroll
            for (int nt = 0; nt < NT; nt++) {
                int nb = nt * 8 + gid;
                float2 b0 = Wbuf[cur][rb0 + nb];
                float2 b1 = Wbuf[cur][rb1 + nb];
                MMA_TF32(acc[nt], ah, __float_as_uint(b0.x), __float_as_uint(b1.x));
                MMA_TF32(acc[nt], ah, __float_as_uint(b0.y), __float_as_uint(b1.y));
                MMA_TF32(acc[nt], al, __float_as_uint(b0.x), __float_as_uint(b1.x));
            }
        }

        // ---- store W(ch+1) into the other buffer; single barrier ----
        if (ch < 8) {
#pragma unroll
            for (int rr = 0; rr < 2; rr++)
#pragma unroll
                for (int q = 0; q < 3; q++) {
                    int cc = lane + 32 * q;
                    if (cc < NT * 8) Wbuf[nxt][(warp * 2 + rr) * LDW2 + cc] = wld[rr][q];
                }
            __syncthreads();
        }
    }

    // ---- epilogue: D thread layout; skip pad cols >= DPAD (half 1, tile 8) ----
    float d0 = va ? rsqrtf((float)g_deg[ra]) : 0.f;
    float d1 = vb ? rsqrtf((float)g_deg[rb]) : 0.f;
#pragma unroll
    for (int nt = 0; nt < NT; nt++) {
        int c0 = NB + nt * 8 + 2 * tig;
        if (c0 < DPAD) {
            if (va)
                *(float2*)(g_hp + (size_t)ra * DPAD + c0) =
                    make_float2(acc[nt][0] * d0, acc[nt][1] * d0);
            if (vb)
                *(float2*)(g_hp + (size_t)rb * DPAD + c0) =
                    make_float2(acc[nt][2] * d1, acc[nt][3] * d1);
        }
    }
}

// ---------------- aggregate: g_feat[i] = relu(dinv[i]*(sum_in hp[j] + hp[i]) + b) ----------------
__global__ void aggregate_kernel(const float* __restrict__ bias, int n) {
    int node = blockIdx.x * (blockDim.x >> 5) + (threadIdx.x >> 5);
    if (node >= n) return;
    int lane = threadIdx.x & 31;

    const float4* self4 = (const float4*)(g_hp + (size_t)node * DPAD);
    float4 acc = self4[lane];
    float4 acct = make_float4(0.f, 0.f, 0.f, 0.f);
    if (lane < 2) acct = self4[32 + lane];

    int s = g_rowptr[node], e = g_rowptr[node + 1];
    int idx = s;
    for (; idx + 1 < e; idx += 2) {
        int j0 = g_col[idx], j1 = g_col[idx + 1];
        const float4* r0 = (const float4*)(g_hp + (size_t)j0 * DPAD);
        const float4* r1 = (const float4*)(g_hp + (size_t)j1 * DPAD);
        float4 v0 = r0[lane];
        float4 v1 = r1[lane];
        float4 t0, t1;
        if (lane < 2) { t0 = r0[32 + lane]; t1 = r1[32 + lane]; }
        acc.x += v0.x; acc.y += v0.y; acc.z += v0.z; acc.w += v0.w;
        acc.x += v1.x; acc.y += v1.y; acc.z += v1.z; acc.w += v1.w;
        if (lane < 2) {
            acct.x += t0.x; acct.y += t0.y; acct.z += t0.z; acct.w += t0.w;
            acct.x += t1.x; acct.y += t1.y; acct.z += t1.z; acct.w += t1.w;
        }
    }
    if (idx < e) {
        int j0 = g_col[idx];
        const float4* r0 = (const float4*)(g_hp + (size_t)j0 * DPAD);
        float4 v0 = r0[lane];
        acc.x += v0.x; acc.y += v0.y; acc.z += v0.z; acc.w += v0.w;
        if (lane < 2) {
            float4 t0 = r0[32 + lane];
            acct.x += t0.x; acct.y += t0.y; acct.z += t0.z; acct.w += t0.w;
        }
    }

    float di = rsqrtf((float)g_deg[node]);
    float4 o;
    o.x = fmaxf(fmaf(acc.x, di, bias[4 * lane + 0]), 0.f);
    o.y = fmaxf(fmaf(acc.y, di, bias[4 * lane + 1]), 0.f);
    o.z = fmaxf(fmaf(acc.z, di, bias[4 * lane + 2]), 0.f);
    o.w = fmaxf(fmaf(acc.w, di, bias[4 * lane + 3]), 0.f);
    float4* out4 = (float4*)(g_feat + (size_t)node * DPAD);
    out4[lane] = o;
    if (lane == 0) {
        float4 t;
        t.x = fmaxf(fmaf(acct.x, di, bias[128]), 0.f);
        t.y = fmaxf(fmaf(acct.y, di, bias[129]), 0.f);
        t.z = fmaxf(fmaf(acct.z, di, bias[130]), 0.f);
        t.w = fmaxf(fmaf(acct.w, di, bias[131]), 0.f);
        out4[32] = t;
    } else if (lane == 1) {
        float4 t;
        t.x = fmaxf(fmaf(acct.x, di, bias[132]), 0.f);
        t.y = 0.f; t.z = 0.f; t.w = 0.f;   // keep pads zero
        out4[33] = t;
    }
}

// ---------------- global mean pool ----------------
__device__ __forceinline__ int lbound_any(const void* a, int n, int v) {
    int lo = 0, hi = n;
    while (lo < hi) {
        int m = (lo + hi) >> 1;
        long long x = g_is64 ? ((const long long*)a)[m]
                             : (long long)((const int*)a)[m];
        if (x < (long long)v) lo = m + 1; else hi = m;
    }
    return lo;
}

__global__ void pool_kernel(const void* __restrict__ batch,
                            float* __restrict__ out, int n) {
    __shared__ int lo_s, hi_s;
    int g = blockIdx.x;
    if (threadIdx.x == 0) {
        lo_s = lbound_any(batch, n, g);
        hi_s = lbound_any(batch, n, g + 1);
    }
    __syncthreads();
    int lo = lo_s, hi = hi_s;
    int c = threadIdx.x;
    if (c < DNF) {
        float s0 = 0.f, s1 = 0.f, s2 = 0.f, s3 = 0.f;
        int r = lo;
        for (; r + 3 < hi; r += 4) {
            s0 += g_feat[(size_t)(r + 0) * DPAD + c];
            s1 += g_feat[(size_t)(r + 1) * DPAD + c];
            s2 += g_feat[(size_t)(r + 2) * DPAD + c];
            s3 += g_feat[(size_t)(r + 3) * DPAD + c];
        }
        for (; r < hi; r++) s0 += g_feat[(size_t)r * DPAD + c];
        int cnt = hi - lo;
        out[g * DNF + c] = ((s0 + s1) + (s2 + s3)) / (float)(cnt > 0 ? cnt : 1);
    }
}

// ---------------- launch: kernel launches ONLY ----------------
extern "C" void kernel_launch(void* const* d_in, const int* in_sizes, int n_in,
                              void* d_out, int out_size) {
    const float* x     = (const float*)d_in[0];
    const void*  ei    = d_in[1];
    const void*  batch = d_in[2];
    const float* W1    = (const float*)d_in[3];
    const float* b1    = (const float*)d_in[4];
    const float* W2    = (const float*)d_in[5];
    const float* b2    = (const float*)d_in[6];
    float* out = (float*)d_out;

    int n = in_sizes[0] / DNF;   // 50000
    int e = in_sizes[1] / 2;     // 800000

    int tb = 256;
    int gn = (n + tb - 1) / tb;  // 196
    int ge = (e + tb - 1) / tb;

    dim3 gemm_grid((n + 127) / 128, 2);   // 391 x 2 halves
    int agg_blocks = (n + 7) / 8;

    prologue_kernel<<<gn, tb>>>((const int*)ei, n);       // 1: deg=1 + dtype detect
    count_deg_kernel<<<ge, tb>>>(ei, e);                  // 2
    wconv_kernel<<<dim3(WDIM, 2), 160>>>(W1, W2);         // 3: tf32 (hi,lo) pack
    gemm_mma_kernel<<<gemm_grid, 256>>>(x, 0, 1, n);      // 4 <- profiled slot
    partial_kernel<<<gn, tb>>>(n);                        // 5
    finalize_kernel<<<gn, tb>>>(n, e);                    // 6: rowptr+pos
    fill_kernel<<<ge, tb>>>(ei, e);                       // 7
    aggregate_kernel<<<agg_blocks, 256>>>(b1, n);         // 8
    gemm_mma_kernel<<<gemm_grid, 256>>>(x, 1, 0, n);      // 9
    aggregate_kernel<<<agg_blocks, 256>>>(b2, n);         // 10
    pool_kernel<<<NGRAPH, 160>>>(batch, out, n);          // 11
}